// round 16
// baseline (speedup 1.0000x reference)
#include <cuda_runtime.h>
#include <cuda_fp16.h>

#define NP 100000
#define KN 16
#define NK (NP*KN)
#define FNK 1600000.f
#define INV_NK (1.f/1600000.f)
#define INV_N  (1.f/100000.f)
#define SEG0 50048

// ---------------- device scratch ----------------
__device__ int      g_cnt[NP];
__device__ float    g_g1[NP*64];
__device__ float    g_g2[NP*64];
__device__ __align__(16) __half g_fph[NP*64];
__device__ float4   g_geo[NP*4];
__device__ float    g_y1w[NK*8];
__device__ unsigned g_y2h[NK*4];
__device__ unsigned g_newh[NP*512];
__device__ unsigned g_lwth[64*512];
__device__ float    g_z[NP*64];
__device__ float    g_stats[512];

#define F1_OFF 0
#define W1_OFF 128
#define F2_OFF 144
#define W2_OFF 272
#define Z_OFF  320
#define W3M_OFF 448       // 8 (S1) + 36 (M upper triangle) = 44 slots

#define EPS_BN 1e-5f

// ---------------- init ----------------
__global__ void k_zero() {
    int i = blockIdx.x * 256 + threadIdx.x;
    if (i < NP)  g_cnt[i] = 0;
    if (i < 512) g_stats[i] = 0.f;
}

__global__ void k_cnt(const int* __restrict__ knn) {
    int i = blockIdx.x * 256 + threadIdx.x;
    if (i < NK) atomicAdd(&g_cnt[knn[i]], 1);
}

// ---------------- geometry pack ----------------
__global__ void k_geo(const float* __restrict__ xyz,
                      const float* __restrict__ cov,
                      const float* __restrict__ feats) {
    int p = blockIdx.x * 256 + threadIdx.x;
    if (p < NP) {
        float x = xyz[3 * p], y = xyz[3 * p + 1], z = xyz[3 * p + 2];
        float nx = feats[(size_t)p * 64 + 3], ny = feats[(size_t)p * 64 + 4], nz = feats[(size_t)p * 64 + 5];
        const float* c = &cov[9 * p];
        g_geo[4 * p + 0] = make_float4(x, y, z, nx);
        g_geo[4 * p + 1] = make_float4(ny, nz, c[0], c[1]);
        g_geo[4 * p + 2] = make_float4(c[2], c[3], c[4], c[5]);
        g_geo[4 * p + 3] = make_float4(c[6], c[7], c[8], 0.f);
    }
}

// ---------------- inline BN finalize ----------------
__device__ __forceinline__ void bn_fin(int off, int nch, float invc,
                                       const float* __restrict__ gamma,
                                       const float* __restrict__ beta,
                                       float* ssc, float* ssh, int t) {
    if (t < nch) {
        float m = g_stats[off + t] * invc;
        float v = g_stats[off + nch + t] * invc - m * m;
        float s = gamma[t] / sqrtf(v + EPS_BN);
        ssc[t] = s;
        ssh[t] = beta[t] - m * s;
    }
}

// ---------------- stats helper ----------------
template<int CH>
__device__ __forceinline__ void stats_reduce(float* ls, float* lss, int off) {
    const unsigned FULL = 0xffffffffu;
    #pragma unroll
    for (int c = 0; c < CH; c++) {
        #pragma unroll
        for (int o = 16; o; o >>= 1) {
            ls[c]  += __shfl_down_sync(FULL, ls[c],  o);
            lss[c] += __shfl_down_sync(FULL, lss[c], o);
        }
    }
    __shared__ float sred[2 * 8 * CH];
    int wid = threadIdx.x >> 5, lane = threadIdx.x & 31;
    if (lane == 0) {
        #pragma unroll
        for (int c = 0; c < CH; c++) {
            sred[wid * CH + c]          = ls[c];
            sred[8 * CH + wid * CH + c] = lss[c];
        }
    }
    __syncthreads();
    if (threadIdx.x < CH) {
        float a = 0.f, b = 0.f;
        #pragma unroll
        for (int w = 0; w < 8; w++) {
            a += sred[w * CH + threadIdx.x];
            b += sred[8 * CH + w * CH + threadIdx.x];
        }
        atomicAdd(&g_stats[off + threadIdx.x], a);
        atomicAdd(&g_stats[off + CH + threadIdx.x], b);
    }
}

// ---------------- fp16 helpers ----------------
__device__ __forceinline__ unsigned packh2(float a, float b) {
    __half2 h = __floats2half2_rn(a, b);
    return *(unsigned*)&h;
}

__device__ __forceinline__ void mma_f16(float* c, unsigned a0, unsigned a1,
                                        unsigned a2, unsigned a3,
                                        unsigned b0, unsigned b1) {
    asm volatile("mma.sync.aligned.m16n8k16.row.col.f32.f16.f16.f32 "
                 "{%0,%1,%2,%3}, {%4,%5,%6,%7}, {%8,%9}, {%0,%1,%2,%3};"
                 : "+f"(c[0]), "+f"(c[1]), "+f"(c[2]), "+f"(c[3])
                 : "r"(a0), "r"(a1), "r"(a2), "r"(a3), "r"(b0), "r"(b1));
}

__device__ __forceinline__ void cp16(void* sptr, const void* gptr) {
    unsigned saddr = (unsigned)__cvta_generic_to_shared(sptr);
    asm volatile("cp.async.cg.shared.global [%0], [%1], 16;" :: "r"(saddr), "l"(gptr));
}

__device__ __forceinline__ unsigned smem_u32x(const void* p) {
    return (unsigned)__cvta_generic_to_shared(p);
}

__device__ __forceinline__ void ldsm_x4_trans(unsigned& r0, unsigned& r1,
                                              unsigned& r2, unsigned& r3, unsigned addr) {
    asm volatile("ldmatrix.sync.aligned.m8n8.x4.trans.shared.b16 {%0,%1,%2,%3}, [%4];"
                 : "=r"(r0), "=r"(r1), "=r"(r2), "=r"(r3) : "r"(addr));
}

__device__ __forceinline__ void ldsm_x2(unsigned& r0, unsigned& r1, unsigned addr) {
    asm volatile("ldmatrix.sync.aligned.m8n8.x2.shared.b16 {%0,%1}, [%2];"
                 : "=r"(r0), "=r"(r1) : "r"(addr));
}

__device__ __forceinline__ int wperm(int j) {
    return ((j & 3) << 1) | (j >> 2);
}

__device__ __forceinline__ void qred4(float& a, float& b, float& c, float& d) {
    const unsigned FULL = 0xffffffffu;
    #pragma unroll
    for (int o = 16; o >= 4; o >>= 1) {
        a += __shfl_down_sync(FULL, a, o);
        b += __shfl_down_sync(FULL, b, o);
        c += __shfl_down_sync(FULL, c, o);
        d += __shfl_down_sync(FULL, d, o);
    }
}

__device__ __forceinline__ float4 shfl_f4(float4 v, int src) {
    const unsigned FULL = 0xffffffffu;
    v.x = __shfl_sync(FULL, v.x, src);
    v.y = __shfl_sync(FULL, v.y, src);
    v.z = __shfl_sync(FULL, v.z, src);
    v.w = __shfl_sync(FULL, v.w, src);
    return v;
}

__device__ __forceinline__ void unpack_y2(int idx, float* a) {
    uint4 pv = *(const uint4*)&g_y2h[idx * 4];
    float2 f0 = __half22float2(*(__half2*)&pv.x);
    float2 f1 = __half22float2(*(__half2*)&pv.y);
    float2 f2 = __half22float2(*(__half2*)&pv.z);
    float2 f3 = __half22float2(*(__half2*)&pv.w);
    a[0] = f0.x; a[1] = f0.y; a[2] = f1.x; a[3] = f1.y;
    a[4] = f2.x; a[5] = f2.y; a[6] = f3.x; a[7] = f3.y;
}

// ---------------- lin_w prep ----------------
__global__ void k_preph(const float* __restrict__ lw) {
    int i = blockIdx.x * 256 + threadIdx.x;
    if (i < 64 * 512) {
        int row = i >> 9, W = i & 511;
        unsigned v = packh2(lw[row * 1024 + 2 * W], lw[row * 1024 + 2 * W + 1]);
        g_lwth[row * 512 + (W & ~7) + wperm(W & 7)] = v;
    }
}

// ---------------- f-path conv via fp16 mma ----------------
#define FP 36
#define FA (128*FP)
#define FB (64*FP)

template<int BN>
__global__ __launch_bounds__(256) void k_fmma32(const float* __restrict__ inF,
                                                const float* __restrict__ wF,
                                                const float* __restrict__ Bb,
                                                float* __restrict__ dst,
                                                int statoff, int bnoff,
                                                const float* __restrict__ gamma,
                                                const float* __restrict__ beta) {
    __shared__ unsigned As[FA];
    __shared__ unsigned Bs[FB];
    __shared__ float sred[128];
    __shared__ float ssc[64], ssh[64];
    int t = threadIdx.x;
    int rbase = blockIdx.x * 128;
    int lane = t & 31, grp = lane >> 2, qid = lane & 3;
    int m0 = (t >> 5) * 16;

    if (BN) bn_fin(bnoff, 64, INV_NK, gamma, beta, ssc, ssh, t);
    if (t < 128) sred[t] = 0.f;
    if (BN) __syncthreads();

    {
        int row = t >> 2, part = t & 3;
        unsigned* bd = &Bs[row * FP];
        const float4* src = (const float4*)&wF[row * 64 + part * 16];
        #pragma unroll
        for (int q = 0; q < 4; q++) {
            float4 v = src[q];
            int c = part * 16 + q * 4;
            int W0 = c >> 1, W1 = W0 + 1;
            bd[(W0 & ~7) + wperm(W0 & 7)] = packh2(v.x, v.y);
            bd[(W1 & ~7) + wperm(W1 & 7)] = packh2(v.z, v.w);
        }
    }

    {
        int row = t >> 1, h16 = t & 1;
        unsigned* ad = &As[row * FP];
        if (rbase + row < NP) {
            const float4* src = (const float4*)&inF[(size_t)(rbase + row) * 64 + h16 * 32];
            #pragma unroll
            for (int q = 0; q < 8; q++) {
                float4 v = src[q];
                int c = h16 * 32 + q * 4;
                if (BN) {
                    v.x = fmaxf(ssc[c + 0] * v.x + ssh[c + 0], 0.f);
                    v.y = fmaxf(ssc[c + 1] * v.y + ssh[c + 1], 0.f);
                    v.z = fmaxf(ssc[c + 2] * v.z + ssh[c + 2], 0.f);
                    v.w = fmaxf(ssc[c + 3] * v.w + ssh[c + 3], 0.f);
                }
                int W0 = c >> 1, W1 = W0 + 1;
                ad[(W0 & ~7) + wperm(W0 & 7)] = packh2(v.x, v.y);
                ad[(W1 & ~7) + wperm(W1 & 7)] = packh2(v.z, v.w);
            }
        } else {
            #pragma unroll
            for (int W = 0; W < 16; W++) ad[h16 * 16 + W] = 0u;
        }
    }
    __syncthreads();

    float cf[8][4];
    #pragma unroll
    for (int nt = 0; nt < 8; nt++)
        #pragma unroll
        for (int j = 0; j < 4; j++) cf[nt][j] = 0.f;

    #pragma unroll
    for (int ks = 0; ks < 4; ks++) {
        uint2 aLo = *(uint2*)&As[(m0 + grp) * FP + ks * 8 + qid * 2];
        uint2 aHi = *(uint2*)&As[(m0 + grp + 8) * FP + ks * 8 + qid * 2];
        #pragma unroll
        for (int nt = 0; nt < 8; nt++) {
            uint2 b = *(uint2*)&Bs[(nt * 8 + grp) * FP + ks * 8 + qid * 2];
            mma_f16(cf[nt], aLo.x, aHi.x, aLo.y, aHi.y, b.x, b.y);
        }
    }

    int r0 = rbase + m0 + grp, r1 = r0 + 8;
    float w0 = (r0 < NP) ? (float)g_cnt[r0] : 0.f;
    float w1v = (r1 < NP) ? (float)g_cnt[r1] : 0.f;
    #pragma unroll
    for (int nt = 0; nt < 8; nt++) {
        int c0 = nt * 8 + 2 * qid;
        float b0v = __ldg(&Bb[c0]), b1v = __ldg(&Bb[c0 + 1]);
        float z0 = cf[nt][0] + b0v, z1 = cf[nt][1] + b1v;
        float z2 = cf[nt][2] + b0v, z3 = cf[nt][3] + b1v;
        if (r0 < NP) *(float2*)&dst[(size_t)r0 * 64 + c0] = make_float2(z0, z1);
        if (r1 < NP) *(float2*)&dst[(size_t)r1 * 64 + c0] = make_float2(z2, z3);
        float s0 = w0 * z0 + w1v * z2;
        float s1 = w0 * z1 + w1v * z3;
        float q0 = w0 * z0 * z0 + w1v * z2 * z2;
        float q1 = w0 * z1 * z1 + w1v * z3 * z3;
        qred4(s0, s1, q0, q1);
        if (lane < 4) {
            atomicAdd(&sred[c0], s0);
            atomicAdd(&sred[c0 + 1], s1);
            atomicAdd(&sred[64 + c0], q0);
            atomicAdd(&sred[64 + c0 + 1], q1);
        }
    }
    __syncthreads();
    if (t < 128) atomicAdd(&g_stats[statoff + t], sred[t]);
}

// ---------------- w-path layer 1: j0 via shuffle; fp32 output ----------------
__global__ __launch_bounds__(256, 3) void k_w1(const int* __restrict__ knn,
                                               const float* __restrict__ ww1,
                                               const float* __restrict__ wb1) {
    __shared__ float wsm[112];
    __shared__ float bsm[8];
    int t = threadIdx.x;
    if (t < 112) wsm[t] = ww1[t];
    if (t < 8)   bsm[t] = wb1[t];
    __syncthreads();
    float ls[8], lss[8];
    #pragma unroll
    for (int o = 0; o < 8; o++) { ls[o] = 0.f; lss[o] = 0.f; }
    int l = t & 31;
    int src0 = l & 16;
    for (int i = blockIdx.x * 256 + t; i < NK; i += gridDim.x * 256) {
        int j = knn[i];
        float4 a0 = g_geo[4 * j + 0], a1 = g_geo[4 * j + 1];
        float4 a2 = g_geo[4 * j + 2], a3 = g_geo[4 * j + 3];
        float4 b0 = shfl_f4(a0, src0);
        float4 b1 = shfl_f4(a1, src0);
        float4 b2 = shfl_f4(a2, src0);
        float4 b3 = shfl_f4(a3, src0);

        float lx = a0.x - b0.x, ly = a0.y - b0.y, lz = a0.z - b0.z;
        float nax = a0.w, nay = a1.x, naz = a1.y;
        float nmx = b0.w, nmy = b1.x, nmz = b1.y;

        float rn = sqrtf(lx * lx + ly * ly + lz * lz);
        float inv = 1.f / fmaxf(rn, 1e-12f);
        float rx = lx * inv, ry = ly * inv, rz = lz * inv;
        float dot = nmx * rx + nmy * ry + nmz * rz;
        float vx = nmx - dot * rx, vy = nmy - dot * ry, vz = nmz - dot * rz;
        float vi = 1.f / fmaxf(sqrtf(vx * vx + vy * vy + vz * vz), 1e-12f);
        vx *= vi; vy *= vi; vz *= vi;
        float wx = ry * vz - rz * vy;
        float wy = rz * vx - rx * vz;
        float wz = rx * vy - ry * vx;
        float wi = 1.f / fmaxf(sqrtf(wx * wx + wy * wy + wz * wz), 1e-12f);
        wx *= wi; wy *= wi; wz *= wi;
        float t1 = nax * nmx + nay * nmy + naz * nmz;
        float t3 = rx * nax + ry * nay + rz * naz;
        float t4 = lx * nmx + ly * nmy + lz * nmz;
        float t6 = nax * vx + nay * vy + naz * vz;
        float t7 = nax * wx + nay * wy + naz * wz;
        float cx = nay * nmz - naz * nmy;
        float cy = naz * nmx - nax * nmz;
        float cz = nax * nmy - nay * nmx;
        float t8 = lx * cx + ly * cy + lz * cz;
        float s1 = lx * (a1.z * lx + a1.w * ly + a2.x * lz)
                 + ly * (a2.y * lx + a2.z * ly + a2.w * lz)
                 + lz * (a3.x * lx + a3.y * ly + a3.z * lz);
        float s2 = lx * (b1.z * lx + b1.w * ly + b2.x * lz)
                 + ly * (b2.y * lx + b2.z * ly + b2.w * lz)
                 + lz * (b3.x * lx + b3.y * ly + b3.z * lz);
        float win[14] = {lx, ly, lz, t1, dot, t3, t4, t3, t6, t7, t8, rn, s1, s2};
        float ya[8];
        #pragma unroll
        for (int o = 0; o < 8; o++) {
            float y = bsm[o];
            #pragma unroll
            for (int c = 0; c < 14; c++) y += wsm[o * 14 + c] * win[c];
            ya[o] = y;
            ls[o] += y; lss[o] += y * y;
        }
        float4* dst = (float4*)&g_y1w[i * 8];
        dst[0] = make_float4(ya[0], ya[1], ya[2], ya[3]);
        dst[1] = make_float4(ya[4], ya[5], ya[6], ya[7]);
    }
    stats_reduce<8>(ls, lss, W1_OFF);
}

// ---------------- w-path layer 2: fp32 in, half out ----------------
__global__ __launch_bounds__(256) void k_w2(const float* __restrict__ ww2,
                                            const float* __restrict__ wb2,
                                            const float* __restrict__ wg1,
                                            const float* __restrict__ wbe1) {
    __shared__ float wsm[64], bsm[8], ssc[8], ssh[8];
    int t = threadIdx.x;
    if (t < 64) wsm[t] = ww2[t];
    if (t < 8)  bsm[t] = wb2[t];
    bn_fin(W1_OFF, 8, INV_NK, wg1, wbe1, ssc, ssh, t);
    __syncthreads();
    float ls[8], lss[8];
    #pragma unroll
    for (int o = 0; o < 8; o++) { ls[o] = 0.f; lss[o] = 0.f; }
    for (int i = blockIdx.x * 256 + t; i < NK; i += gridDim.x * 256) {
        float a[8];
        float4 a0 = *(const float4*)&g_y1w[i * 8];
        float4 a1 = *(const float4*)&g_y1w[i * 8 + 4];
        a[0] = a0.x; a[1] = a0.y; a[2] = a0.z; a[3] = a0.w;
        a[4] = a1.x; a[5] = a1.y; a[6] = a1.z; a[7] = a1.w;
        #pragma unroll
        for (int c = 0; c < 8; c++) a[c] = fmaxf(ssc[c] * a[c] + ssh[c], 0.f);
        float ya[8];
        #pragma unroll
        for (int o = 0; o < 8; o++) {
            float y = bsm[o];
            #pragma unroll
            for (int c = 0; c < 8; c++) y += wsm[o * 8 + c] * a[c];
            ya[o] = y;
            ls[o] += y; lss[o] += y * y;
        }
        uint4 pv;
        pv.x = packh2(ya[0], ya[1]);
        pv.y = packh2(ya[2], ya[3]);
        pv.z = packh2(ya[4], ya[5]);
        pv.w = packh2(ya[6], ya[7]);
        *(uint4*)&g_y2h[i * 4] = pv;
    }
    stats_reduce<8>(ls, lss, W2_OFF);
}

// ---------------- w-path layer 3: MOMENTS of a = relu(BN2(y2)) ----------------
// Accumulates S1[8] and upper-triangle M[36]; W3 stats reconstructed in k_newmma.
__global__ __launch_bounds__(256) void k_w3m(const float* __restrict__ wg2,
                                             const float* __restrict__ wbe2) {
    __shared__ float ssc[8], ssh[8];
    __shared__ float sred[8 * 44];
    int t = threadIdx.x;
    bn_fin(W2_OFF, 8, INV_NK, wg2, wbe2, ssc, ssh, t);
    __syncthreads();
    float acc[44];
    #pragma unroll
    for (int i = 0; i < 44; i++) acc[i] = 0.f;
    for (int i = blockIdx.x * 256 + t; i < NK; i += gridDim.x * 256) {
        float a[8];
        unpack_y2(i, a);
        #pragma unroll
        for (int c = 0; c < 8; c++) a[c] = fmaxf(ssc[c] * a[c] + ssh[c], 0.f);
        #pragma unroll
        for (int c = 0; c < 8; c++) acc[c] += a[c];
        int idx = 8;
        #pragma unroll
        for (int c = 0; c < 8; c++)
            #pragma unroll
            for (int d = 0; d <= c; d++)
                acc[idx++] += a[c] * a[d];
    }
    const unsigned FULL = 0xffffffffu;
    #pragma unroll
    for (int i = 0; i < 44; i++) {
        #pragma unroll
        for (int o = 16; o; o >>= 1)
            acc[i] += __shfl_down_sync(FULL, acc[i], o);
    }
    int wid = t >> 5, lane = t & 31;
    if (lane == 0) {
        #pragma unroll
        for (int i = 0; i < 44; i++) sred[wid * 44 + i] = acc[i];
    }
    __syncthreads();
    if (t < 44) {
        float s = 0.f;
        #pragma unroll
        for (int w = 0; w < 8; w++) s += sred[w * 44 + t];
        atomicAdd(&g_stats[W3M_OFF + t], s);
    }
}

// ---------------- fpost ----------------
__global__ void k_post(const float* __restrict__ fg2, const float* __restrict__ fbe2) {
    __shared__ float ssc[64], ssh[64];
    int t = threadIdx.x;
    bn_fin(F2_OFF, 64, INV_NK, fg2, fbe2, ssc, ssh, t);
    __syncthreads();
    int i = blockIdx.x * 256 + t;
    if (i < NP * 32) {
        int c = (2 * i) & 63;
        float y0 = g_g2[2 * i],     y1 = g_g2[2 * i + 1];
        y0 = fmaxf(ssc[c] * y0 + ssh[c], 0.f);
        y1 = fmaxf(ssc[c + 1] * y1 + ssh[c + 1], 0.f);
        *(unsigned*)&g_fph[2 * i] = packh2(y0, y1);
    }
}

// ---------------- new = f @ w^T per point, tensor cores (segmented) ----------------
__global__ __launch_bounds__(256) void k_newmma(int nbase,
                                                const int* __restrict__ knn,
                                                const float* __restrict__ ww3,
                                                const float* __restrict__ wb3,
                                                const float* __restrict__ wg2,
                                                const float* __restrict__ wbe2,
                                                const float* __restrict__ wg3,
                                                const float* __restrict__ wbe3) {
    __shared__ __align__(16) __half st[8][16 * 72];
    __shared__ __align__(16) __half ws[8][16 * 24];
    __shared__ float sww3[128], swb3[16], sc3[16], sh3[16], sc2[8], sh2[8];
    int t = threadIdx.x, w = t >> 5, l = t & 31;
    if (t < 128) sww3[t] = ww3[t];
    if (t < 16)  swb3[t] = wb3[t];
    // W3 scale/shift from moments: sum = NK*b + w.S1 ; sumsq = w'Mw + 2b(w.S1) + NK*b^2
    if (t < 16) {
        float wv[8];
        #pragma unroll
        for (int c = 0; c < 8; c++) wv[c] = __ldg(&ww3[t * 8 + c]);
        float b = __ldg(&wb3[t]);
        float s1dot = 0.f;
        #pragma unroll
        for (int c = 0; c < 8; c++) s1dot += wv[c] * g_stats[W3M_OFF + c];
        float quad = 0.f;
        int idx = 8;
        #pragma unroll
        for (int c = 0; c < 8; c++)
            #pragma unroll
            for (int d = 0; d <= c; d++) {
                float coef = (c == d) ? wv[c] * wv[c] : 2.f * wv[c] * wv[d];
                quad += coef * g_stats[W3M_OFF + idx++];
            }
        float ssum = FNK * b + s1dot;
        float ssq  = quad + 2.f * b * s1dot + FNK * b * b;
        float mean = ssum * INV_NK;
        float var  = ssq * INV_NK - mean * mean;
        float s = __ldg(&wg3[t]) / sqrtf(var + EPS_BN);
        sc3[t] = s;
        sh3[t] = __ldg(&wbe3[t]) - mean * s;
    }
    if (t >= 32 && t < 40) {
        int c = t - 32;
        float m = g_stats[W2_OFF + c] * INV_NK;
        float v = g_stats[W2_OFF + 8 + c] * INV_NK - m * m;
        float s = wg2[c] / sqrtf(v + EPS_BN);
        sc2[c] = s;
        sh2[c] = wbe2[c] - m * s;
    }
    __syncthreads();

    int n = nbase + blockIdx.x * 8 + w;
    int sjv = knn[n * 16 + (l & 15)];
    int jj = __shfl_sync(0xffffffffu, sjv, l >> 1);

    {
        const uint4* src = (const uint4*)(g_fph + (size_t)jj * 64 + (l & 1) * 32);
        uint4* dst = (uint4*)&st[w][(l >> 1) * 72 + (l & 1) * 32];
        dst[0] = src[0]; dst[1] = src[1]; dst[2] = src[2]; dst[3] = src[3];
    }

    if (l < 16) {
        float a[8];
        unpack_y2(n * 16 + l, a);
        #pragma unroll
        for (int c = 0; c < 8; c++) a[c] = fmaxf(sc2[c] * a[c] + sh2[c], 0.f);
        #pragma unroll
        for (int m = 0; m < 16; m++) {
            float y = swb3[m];
            #pragma unroll
            for (int c = 0; c < 8; c++) y += sww3[m * 8 + c] * a[c];
            ws[w][m * 24 + l] = __float2half(fmaxf(sc3[m] * y + sh3[m], 0.f));
        }
    }
    __syncwarp();

    unsigned bf[2][2];
    #pragma unroll
    for (int mg = 0; mg < 2; mg++) {
        int q = l & 15;
        unsigned addr = smem_u32x(&ws[w][(mg * 8 + (q & 7)) * 24 + (q >> 3) * 8]);
        ldsm_x2(bf[mg][0], bf[mg][1], addr);
    }

    float d[4][2][4] = {};
    int matid = l >> 3;
    int krow = (l & 7) + ((matid >> 1) << 3);
    int coff = (matid & 1) * 8;

    #pragma unroll
    for (int hg = 0; hg < 4; hg++) {
        unsigned a0, a1, a2, a3;
        unsigned addr = smem_u32x(&st[w][krow * 72 + hg * 16 + coff]);
        ldsm_x4_trans(a0, a1, a2, a3, addr);
        #pragma unroll
        for (int mg = 0; mg < 2; mg++)
            mma_f16(d[hg][mg], a0, a1, a2, a3, bf[mg][0], bf[mg][1]);
    }

    int g = l >> 2, tt = l & 3;
    unsigned* row = g_newh + (size_t)n * 512;
    #pragma unroll
    for (int hg = 0; hg < 4; hg++) {
        int h = hg * 16 + g;
        #pragma unroll
        for (int mg = 0; mg < 2; mg++) {
            int pos = wperm(mg * 4 + tt);
            row[h * 8 + pos]       = packh2(d[hg][mg][0], d[hg][mg][1]);
            row[(h + 8) * 8 + pos] = packh2(d[hg][mg][2], d[hg][mg][3]);
        }
    }
}

// ---------------- GEMM (segmented) ----------------
#define GP 36
#define GA (128*GP)
#define GB (64*GP)
#define SMEM_G ((2*GA + 2*GB)*4)

__global__ __launch_bounds__(256, 3) void k_gemm(int nbase, const float* __restrict__ lb) {
    extern __shared__ unsigned sm[];
    unsigned* As[2] = { sm, sm + GA };
    unsigned* Bs[2] = { sm + 2 * GA, sm + 2 * GA + GB };
    __shared__ float sred[128];
    int t = threadIdx.x;
    int rbase = nbase + blockIdx.x * 128;
    int lane = t & 31, grp = lane >> 2, qid = lane & 3;
    int m0 = (t >> 5) * 16;

    if (rbase + 128 > NP) {
        for (int i = t; i < 2 * GA; i += 256) sm[i] = 0u;
        __syncthreads();
    }
    if (t < 128) sred[t] = 0.f;

    float cf[8][4];
    #pragma unroll
    for (int nt = 0; nt < 8; nt++)
        #pragma unroll
        for (int j = 0; j < 4; j++) cf[nt][j] = 0.f;

    auto load = [&](int buf, int s) {
        int kc = s * 32;
        #pragma unroll
        for (int r4 = 0; r4 < 4; r4++) {
            int seg = t + r4 * 256;
            int row = seg >> 3, w16 = seg & 7;
            if (rbase + row < NP)
                cp16(As[buf] + row * GP + w16 * 4,
                     g_newh + (size_t)(rbase + row) * 512 + kc + w16 * 4);
        }
        #pragma unroll
        for (int r2 = 0; r2 < 2; r2++) {
            int seg = t + r2 * 256;
            int row = seg >> 3, w16 = seg & 7;
            cp16(Bs[buf] + row * GP + w16 * 4,
                 g_lwth + row * 512 + kc + w16 * 4);
        }
        asm volatile("cp.async.commit_group;");
    };

    load(0, 0);
    int cur = 0;
    for (int s = 0; s < 16; s++) {
        if (s < 15) {
            load(cur ^ 1, s + 1);
            asm volatile("cp.async.wait_group 1;");
        } else {
            asm volatile("cp.async.wait_group 0;");
        }
        __syncthreads();
        unsigned* A = As[cur];
        unsigned* B = Bs[cur];
        #pragma unroll
        for (int ks = 0; ks < 4; ks++) {
            uint2 aLo = *(uint2*)&A[(m0 + grp) * GP + ks * 8 + qid * 2];
            uint2 aHi = *(uint2*)&A[(m0 + grp + 8) * GP + ks * 8 + qid * 2];
            #pragma unroll
            for (int nt = 0; nt < 8; nt++) {
                uint2 b = *(uint2*)&B[(nt * 8 + grp) * GP + ks * 8 + qid * 2];
                mma_f16(cf[nt], aLo.x, aHi.x, aLo.y, aHi.y, b.x, b.y);
            }
        }
        __syncthreads();
        cur ^= 1;
    }

    int r0 = rbase + m0 + grp, r1 = r0 + 8;
    bool v0 = r0 < NP, v1 = r1 < NP;
    #pragma unroll
    for (int nt = 0; nt < 8; nt++) {
        int c0 = nt * 8 + 2 * qid;
        float b0v = __ldg(&lb[c0]), b1v = __ldg(&lb[c0 + 1]);
        float z0 = cf[nt][0] + b0v, z1 = cf[nt][1] + b1v;
        float z2 = cf[nt][2] + b0v, z3 = cf[nt][3] + b1v;
        float s0 = 0.f, s1 = 0.f, q0 = 0.f, q1 = 0.f;
        if (v0) {
            *(float2*)&g_z[r0 * 64 + c0] = make_float2(z0, z1);
            s0 += z0; s1 += z1; q0 += z0 * z0; q1 += z1 * z1;
        }
        if (v1) {
            *(float2*)&g_z[r1 * 64 + c0] = make_float2(z2, z3);
            s0 += z2; s1 += z3; q0 += z2 * z2; q1 += z3 * z3;
        }
        qred4(s0, s1, q0, q1);
        if (lane < 4) {
            atomicAdd(&sred[c0], s0);
            atomicAdd(&sred[c0 + 1], s1);
            atomicAdd(&sred[64 + c0], q0);
            atomicAdd(&sred[64 + c0 + 1], q1);
        }
    }
    __syncthreads();
    if (t < 128) atomicAdd(&g_stats[Z_OFF + t], sred[t]);
}

// ---------------- final BN + relu -> output (float4) ----------------
__global__ void k_out(float* __restrict__ out,
                      const float* __restrict__ bng, const float* __restrict__ bnb) {
    __shared__ float ssc[64], ssh[64];
    int t = threadIdx.x;
    bn_fin(Z_OFF, 64, INV_N, bng, bnb, ssc, ssh, t);
    __syncthreads();
    int i = blockIdx.x * 256 + t;
    if (i < NP * 16) {
        int c = (i * 4) & 63;
        float4 v = *(const float4*)&g_z[i * 4];
        v.x = fmaxf(ssc[c + 0] * v.x + ssh[c + 0], 0.f);
        v.y = fmaxf(ssc[c + 1] * v.y + ssh[c + 1], 0.f);
        v.z = fmaxf(ssc[c + 2] * v.z + ssh[c + 2], 0.f);
        v.w = fmaxf(ssc[c + 3] * v.w + ssh[c + 3], 0.f);
        *(float4*)&out[i * 4] = v;
    }
}

// ---------------- stream/event infra ----------------
static cudaStream_t g_sF = nullptr;
static cudaEvent_t  g_eFork = nullptr, g_eJoin = nullptr;
static cudaEvent_t  g_eN0 = nullptr, g_eN1 = nullptr, g_eG = nullptr;
static int g_stream_init = ([]() {
    cudaStreamCreateWithFlags(&g_sF, cudaStreamNonBlocking);
    cudaEventCreateWithFlags(&g_eFork, cudaEventDisableTiming);
    cudaEventCreateWithFlags(&g_eJoin, cudaEventDisableTiming);
    cudaEventCreateWithFlags(&g_eN0, cudaEventDisableTiming);
    cudaEventCreateWithFlags(&g_eN1, cudaEventDisableTiming);
    cudaEventCreateWithFlags(&g_eG, cudaEventDisableTiming);
    return 0;
})();

// ---------------- launch ----------------
extern "C" void kernel_launch(void* const* d_in, const int* in_sizes, int n_in,
                              void* d_out, int out_size) {
    const float* xyz   = (const float*)d_in[0];
    const float* cov   = (const float*)d_in[1];
    const float* feats = (const float*)d_in[2];
    const int*   knn   = (const int*)  d_in[3];
    const float* fw1 = (const float*)d_in[4];
    const float* fb1 = (const float*)d_in[5];
    const float* fg1 = (const float*)d_in[6];
    const float* fbe1 = (const float*)d_in[7];
    const float* fw2 = (const float*)d_in[8];
    const float* fb2 = (const float*)d_in[9];
    const float* fg2 = (const float*)d_in[10];
    const float* fbe2 = (const float*)d_in[11];
    const float* ww1 = (const float*)d_in[12];
    const float* wb1 = (const float*)d_in[13];
    const float* wg1 = (const float*)d_in[14];
    const float* wbe1 = (const float*)d_in[15];
    const float* ww2 = (const float*)d_in[16];
    const float* wb2 = (const float*)d_in[17];
    const float* wg2 = (const float*)d_in[18];
    const float* wbe2 = (const float*)d_in[19];
    const float* ww3 = (const float*)d_in[20];
    const float* wb3 = (const float*)d_in[21];
    const float* wg3 = (const float*)d_in[22];
    const float* wbe3 = (const float*)d_in[23];
    const float* lin_w = (const float*)d_in[24];
    const float* lin_b = (const float*)d_in[25];
    const float* bng = (const float*)d_in[26];
    const float* bnb = (const float*)d_in[27];
    float* out = (float*)d_out;

    float* d_g1; cudaGetSymbolAddress((void**)&d_g1, g_g1);
    float* d_g2; cudaGetSymbolAddress((void**)&d_g2, g_g2);

    cudaFuncSetAttribute(k_gemm, cudaFuncAttributeMaxDynamicSharedMemorySize, SMEM_G);

    cudaStream_t sF = g_sF;
    const int NBLK = (NP + 127) / 128;
    const int NB0 = SEG0 / 128;
    const int NB1 = NBLK - NB0;
    const int NM0 = SEG0 / 8;
    const int NM1 = (NP - SEG0) / 8;

    // ---- common init on main stream ----
    k_zero<<<(NP + 255) / 256, 256>>>();
    cudaEventRecord(g_eFork, 0);
    cudaStreamWaitEvent(sF, g_eFork, 0);

    // ---- w-path on main stream ----
    k_geo<<<(NP + 255) / 256, 256>>>(xyz, cov, feats);
    k_w1<<<2048, 256>>>(knn, ww1, wb1);
    k_w2<<<2048, 256>>>(ww2, wb2, wg1, wbe1);
    k_w3m<<<2048, 256>>>(wg2, wbe2);
    k_preph<<<128, 256>>>(lin_w);

    // ---- fork: counts + f-path on sF (concurrent with w-path) ----
    k_cnt<<<(NK + 255) / 256, 256, 0, sF>>>(knn);
    k_fmma32<0><<<NBLK, 256, 0, sF>>>(feats, fw1, fb1, d_g1, F1_OFF, 0, nullptr, nullptr);
    k_fmma32<1><<<NBLK, 256, 0, sF>>>(d_g1, fw2, fb2, d_g2, F2_OFF, F1_OFF, fg1, fbe1);
    k_post<<<(NP * 32 + 255) / 256, 256, 0, sF>>>(fg2, fbe2);
    cudaEventRecord(g_eJoin, sF);

    // ---- join: main waits for f-chain ----
    cudaStreamWaitEvent(0, g_eJoin, 0);

    // ---- segmented einsum + GEMM with cross-stream overlap ----
    k_newmma<<<NM0, 256>>>(0, knn, ww3, wb3, wg2, wbe2, wg3, wbe3);
    cudaEventRecord(g_eN0, 0);
    k_newmma<<<NM1, 256>>>(SEG0, knn, ww3, wb3, wg2, wbe2, wg3, wbe3);
    cudaEventRecord(g_eN1, 0);

    cudaStreamWaitEvent(sF, g_eN0, 0);
    k_gemm<<<NB0, 256, SMEM_G, sF>>>(0, lin_b);
    cudaStreamWaitEvent(sF, g_eN1, 0);
    k_gemm<<<NB1, 256, SMEM_G, sF>>>(SEG0, lin_b);
    cudaEventRecord(g_eG, sF);

    cudaStreamWaitEvent(0, g_eG, 0);
    k_out<<<(NP * 16 + 255) / 256, 256>>>(out, bng, bnb);
}

// round 17
// speedup vs baseline: 1.4521x; 1.4521x over previous
#include <cuda_runtime.h>
#include <cuda_fp16.h>

#define NP 100000
#define KN 16
#define NK (NP*KN)
#define INV_NK (1.f/1600000.f)
#define INV_N  (1.f/100000.f)
#define SEG0 50048

// ---------------- device scratch ----------------
__device__ int      g_cnt[NP];
__device__ float    g_g1[NP*64];
__device__ float    g_g2[NP*64];
__device__ __align__(16) __half g_fph[NP*64];
__device__ float4   g_geo[NP*4];
__device__ float    g_y1w[NK*8];
__device__ unsigned g_y2h[NK*4];
__device__ unsigned g_newh[NP*512];
__device__ unsigned g_lwth[64*512];
__device__ float    g_z[NP*64];
__device__ float    g_stats[448];

#define F1_OFF 0
#define W1_OFF 128
#define F2_OFF 144
#define W2_OFF 272
#define W3_OFF 288
#define Z_OFF  320

#define EPS_BN 1e-5f

// ---------------- init ----------------
__global__ void k_zero() {
    int i = blockIdx.x * 256 + threadIdx.x;
    if (i < NP)  g_cnt[i] = 0;
    if (i < 448) g_stats[i] = 0.f;
}

__global__ void k_cnt(const int* __restrict__ knn) {
    int i = blockIdx.x * 256 + threadIdx.x;
    if (i < NK) atomicAdd(&g_cnt[knn[i]], 1);
}

// ---------------- geometry pack ----------------
__global__ void k_geo(const float* __restrict__ xyz,
                      const float* __restrict__ cov,
                      const float* __restrict__ feats) {
    int p = blockIdx.x * 256 + threadIdx.x;
    if (p < NP) {
        float x = xyz[3 * p], y = xyz[3 * p + 1], z = xyz[3 * p + 2];
        float nx = feats[(size_t)p * 64 + 3], ny = feats[(size_t)p * 64 + 4], nz = feats[(size_t)p * 64 + 5];
        const float* c = &cov[9 * p];
        g_geo[4 * p + 0] = make_float4(x, y, z, nx);
        g_geo[4 * p + 1] = make_float4(ny, nz, c[0], c[1]);
        g_geo[4 * p + 2] = make_float4(c[2], c[3], c[4], c[5]);
        g_geo[4 * p + 3] = make_float4(c[6], c[7], c[8], 0.f);
    }
}

// ---------------- inline BN finalize ----------------
__device__ __forceinline__ void bn_fin(int off, int nch, float invc,
                                       const float* __restrict__ gamma,
                                       const float* __restrict__ beta,
                                       float* ssc, float* ssh, int t) {
    if (t < nch) {
        float m = g_stats[off + t] * invc;
        float v = g_stats[off + nch + t] * invc - m * m;
        float s = gamma[t] / sqrtf(v + EPS_BN);
        ssc[t] = s;
        ssh[t] = beta[t] - m * s;
    }
}

// ---------------- stats helper ----------------
template<int CH>
__device__ __forceinline__ void stats_reduce(float* ls, float* lss, int off) {
    const unsigned FULL = 0xffffffffu;
    #pragma unroll
    for (int c = 0; c < CH; c++) {
        #pragma unroll
        for (int o = 16; o; o >>= 1) {
            ls[c]  += __shfl_down_sync(FULL, ls[c],  o);
            lss[c] += __shfl_down_sync(FULL, lss[c], o);
        }
    }
    __shared__ float sred[2 * 8 * CH];
    int wid = threadIdx.x >> 5, lane = threadIdx.x & 31;
    if (lane == 0) {
        #pragma unroll
        for (int c = 0; c < CH; c++) {
            sred[wid * CH + c]          = ls[c];
            sred[8 * CH + wid * CH + c] = lss[c];
        }
    }
    __syncthreads();
    if (threadIdx.x < CH) {
        float a = 0.f, b = 0.f;
        #pragma unroll
        for (int w = 0; w < 8; w++) {
            a += sred[w * CH + threadIdx.x];
            b += sred[8 * CH + w * CH + threadIdx.x];
        }
        atomicAdd(&g_stats[off + threadIdx.x], a);
        atomicAdd(&g_stats[off + CH + threadIdx.x], b);
    }
}

// ---------------- fp16 helpers ----------------
__device__ __forceinline__ unsigned packh2(float a, float b) {
    __half2 h = __floats2half2_rn(a, b);
    return *(unsigned*)&h;
}

__device__ __forceinline__ void mma_f16(float* c, unsigned a0, unsigned a1,
                                        unsigned a2, unsigned a3,
                                        unsigned b0, unsigned b1) {
    asm volatile("mma.sync.aligned.m16n8k16.row.col.f32.f16.f16.f32 "
                 "{%0,%1,%2,%3}, {%4,%5,%6,%7}, {%8,%9}, {%0,%1,%2,%3};"
                 : "+f"(c[0]), "+f"(c[1]), "+f"(c[2]), "+f"(c[3])
                 : "r"(a0), "r"(a1), "r"(a2), "r"(a3), "r"(b0), "r"(b1));
}

__device__ __forceinline__ void cp16(void* sptr, const void* gptr) {
    unsigned saddr = (unsigned)__cvta_generic_to_shared(sptr);
    asm volatile("cp.async.cg.shared.global [%0], [%1], 16;" :: "r"(saddr), "l"(gptr));
}

__device__ __forceinline__ unsigned smem_u32x(const void* p) {
    return (unsigned)__cvta_generic_to_shared(p);
}

__device__ __forceinline__ void ldsm_x4_trans(unsigned& r0, unsigned& r1,
                                              unsigned& r2, unsigned& r3, unsigned addr) {
    asm volatile("ldmatrix.sync.aligned.m8n8.x4.trans.shared.b16 {%0,%1,%2,%3}, [%4];"
                 : "=r"(r0), "=r"(r1), "=r"(r2), "=r"(r3) : "r"(addr));
}

__device__ __forceinline__ void ldsm_x2(unsigned& r0, unsigned& r1, unsigned addr) {
    asm volatile("ldmatrix.sync.aligned.m8n8.x2.shared.b16 {%0,%1}, [%2];"
                 : "=r"(r0), "=r"(r1) : "r"(addr));
}

__device__ __forceinline__ int wperm(int j) {
    return ((j & 3) << 1) | (j >> 2);
}

__device__ __forceinline__ void qred4(float& a, float& b, float& c, float& d) {
    const unsigned FULL = 0xffffffffu;
    #pragma unroll
    for (int o = 16; o >= 4; o >>= 1) {
        a += __shfl_down_sync(FULL, a, o);
        b += __shfl_down_sync(FULL, b, o);
        c += __shfl_down_sync(FULL, c, o);
        d += __shfl_down_sync(FULL, d, o);
    }
}

__device__ __forceinline__ float4 shfl_f4(float4 v, int src) {
    const unsigned FULL = 0xffffffffu;
    v.x = __shfl_sync(FULL, v.x, src);
    v.y = __shfl_sync(FULL, v.y, src);
    v.z = __shfl_sync(FULL, v.z, src);
    v.w = __shfl_sync(FULL, v.w, src);
    return v;
}

__device__ __forceinline__ void unpack_y2(int idx, float* a) {
    uint4 pv = *(const uint4*)&g_y2h[idx * 4];
    float2 f0 = __half22float2(*(__half2*)&pv.x);
    float2 f1 = __half22float2(*(__half2*)&pv.y);
    float2 f2 = __half22float2(*(__half2*)&pv.z);
    float2 f3 = __half22float2(*(__half2*)&pv.w);
    a[0] = f0.x; a[1] = f0.y; a[2] = f1.x; a[3] = f1.y;
    a[4] = f2.x; a[5] = f2.y; a[6] = f3.x; a[7] = f3.y;
}

// ---------------- lin_w prep ----------------
__global__ void k_preph(const float* __restrict__ lw) {
    int i = blockIdx.x * 256 + threadIdx.x;
    if (i < 64 * 512) {
        int row = i >> 9, W = i & 511;
        unsigned v = packh2(lw[row * 1024 + 2 * W], lw[row * 1024 + 2 * W + 1]);
        g_lwth[row * 512 + (W & ~7) + wperm(W & 7)] = v;
    }
}

// ---------------- f-path conv via fp16 mma ----------------
#define FP 36
#define FA (128*FP)
#define FB (64*FP)

template<int BN>
__global__ __launch_bounds__(256) void k_fmma32(const float* __restrict__ inF,
                                                const float* __restrict__ wF,
                                                const float* __restrict__ Bb,
                                                float* __restrict__ dst,
                                                int statoff, int bnoff,
                                                const float* __restrict__ gamma,
                                                const float* __restrict__ beta) {
    __shared__ unsigned As[FA];
    __shared__ unsigned Bs[FB];
    __shared__ float sred[128];
    __shared__ float ssc[64], ssh[64];
    int t = threadIdx.x;
    int rbase = blockIdx.x * 128;
    int lane = t & 31, grp = lane >> 2, qid = lane & 3;
    int m0 = (t >> 5) * 16;

    if (BN) bn_fin(bnoff, 64, INV_NK, gamma, beta, ssc, ssh, t);
    if (t < 128) sred[t] = 0.f;
    if (BN) __syncthreads();

    {
        int row = t >> 2, part = t & 3;
        unsigned* bd = &Bs[row * FP];
        const float4* src = (const float4*)&wF[row * 64 + part * 16];
        #pragma unroll
        for (int q = 0; q < 4; q++) {
            float4 v = src[q];
            int c = part * 16 + q * 4;
            int W0 = c >> 1, W1 = W0 + 1;
            bd[(W0 & ~7) + wperm(W0 & 7)] = packh2(v.x, v.y);
            bd[(W1 & ~7) + wperm(W1 & 7)] = packh2(v.z, v.w);
        }
    }

    {
        int row = t >> 1, h16 = t & 1;
        unsigned* ad = &As[row * FP];
        if (rbase + row < NP) {
            const float4* src = (const float4*)&inF[(size_t)(rbase + row) * 64 + h16 * 32];
            #pragma unroll
            for (int q = 0; q < 8; q++) {
                float4 v = src[q];
                int c = h16 * 32 + q * 4;
                if (BN) {
                    v.x = fmaxf(ssc[c + 0] * v.x + ssh[c + 0], 0.f);
                    v.y = fmaxf(ssc[c + 1] * v.y + ssh[c + 1], 0.f);
                    v.z = fmaxf(ssc[c + 2] * v.z + ssh[c + 2], 0.f);
                    v.w = fmaxf(ssc[c + 3] * v.w + ssh[c + 3], 0.f);
                }
                int W0 = c >> 1, W1 = W0 + 1;
                ad[(W0 & ~7) + wperm(W0 & 7)] = packh2(v.x, v.y);
                ad[(W1 & ~7) + wperm(W1 & 7)] = packh2(v.z, v.w);
            }
        } else {
            #pragma unroll
            for (int W = 0; W < 16; W++) ad[h16 * 16 + W] = 0u;
        }
    }
    __syncthreads();

    float cf[8][4];
    #pragma unroll
    for (int nt = 0; nt < 8; nt++)
        #pragma unroll
        for (int j = 0; j < 4; j++) cf[nt][j] = 0.f;

    #pragma unroll
    for (int ks = 0; ks < 4; ks++) {
        uint2 aLo = *(uint2*)&As[(m0 + grp) * FP + ks * 8 + qid * 2];
        uint2 aHi = *(uint2*)&As[(m0 + grp + 8) * FP + ks * 8 + qid * 2];
        #pragma unroll
        for (int nt = 0; nt < 8; nt++) {
            uint2 b = *(uint2*)&Bs[(nt * 8 + grp) * FP + ks * 8 + qid * 2];
            mma_f16(cf[nt], aLo.x, aHi.x, aLo.y, aHi.y, b.x, b.y);
        }
    }

    int r0 = rbase + m0 + grp, r1 = r0 + 8;
    float w0 = (r0 < NP) ? (float)g_cnt[r0] : 0.f;
    float w1v = (r1 < NP) ? (float)g_cnt[r1] : 0.f;
    #pragma unroll
    for (int nt = 0; nt < 8; nt++) {
        int c0 = nt * 8 + 2 * qid;
        float b0v = __ldg(&Bb[c0]), b1v = __ldg(&Bb[c0 + 1]);
        float z0 = cf[nt][0] + b0v, z1 = cf[nt][1] + b1v;
        float z2 = cf[nt][2] + b0v, z3 = cf[nt][3] + b1v;
        if (r0 < NP) *(float2*)&dst[(size_t)r0 * 64 + c0] = make_float2(z0, z1);
        if (r1 < NP) *(float2*)&dst[(size_t)r1 * 64 + c0] = make_float2(z2, z3);
        float s0 = w0 * z0 + w1v * z2;
        float s1 = w0 * z1 + w1v * z3;
        float q0 = w0 * z0 * z0 + w1v * z2 * z2;
        float q1 = w0 * z1 * z1 + w1v * z3 * z3;
        qred4(s0, s1, q0, q1);
        if (lane < 4) {
            atomicAdd(&sred[c0], s0);
            atomicAdd(&sred[c0 + 1], s1);
            atomicAdd(&sred[64 + c0], q0);
            atomicAdd(&sred[64 + c0 + 1], q1);
        }
    }
    __syncthreads();
    if (t < 128) atomicAdd(&g_stats[statoff + t], sred[t]);
}

// ---------------- w-path layer 1: j0 via shuffle; fp32 output ----------------
__global__ __launch_bounds__(256, 3) void k_w1(const int* __restrict__ knn,
                                               const float* __restrict__ ww1,
                                               const float* __restrict__ wb1) {
    __shared__ float wsm[112];
    __shared__ float bsm[8];
    int t = threadIdx.x;
    if (t < 112) wsm[t] = ww1[t];
    if (t < 8)   bsm[t] = wb1[t];
    __syncthreads();
    float ls[8], lss[8];
    #pragma unroll
    for (int o = 0; o < 8; o++) { ls[o] = 0.f; lss[o] = 0.f; }
    int l = t & 31;
    int src0 = l & 16;
    for (int i = blockIdx.x * 256 + t; i < NK; i += gridDim.x * 256) {
        int j = knn[i];
        float4 a0 = g_geo[4 * j + 0], a1 = g_geo[4 * j + 1];
        float4 a2 = g_geo[4 * j + 2], a3 = g_geo[4 * j + 3];
        float4 b0 = shfl_f4(a0, src0);
        float4 b1 = shfl_f4(a1, src0);
        float4 b2 = shfl_f4(a2, src0);
        float4 b3 = shfl_f4(a3, src0);

        float lx = a0.x - b0.x, ly = a0.y - b0.y, lz = a0.z - b0.z;
        float nax = a0.w, nay = a1.x, naz = a1.y;
        float nmx = b0.w, nmy = b1.x, nmz = b1.y;

        float rn = sqrtf(lx * lx + ly * ly + lz * lz);
        float inv = 1.f / fmaxf(rn, 1e-12f);
        float rx = lx * inv, ry = ly * inv, rz = lz * inv;
        float dot = nmx * rx + nmy * ry + nmz * rz;
        float vx = nmx - dot * rx, vy = nmy - dot * ry, vz = nmz - dot * rz;
        float vi = 1.f / fmaxf(sqrtf(vx * vx + vy * vy + vz * vz), 1e-12f);
        vx *= vi; vy *= vi; vz *= vi;
        float wx = ry * vz - rz * vy;
        float wy = rz * vx - rx * vz;
        float wz = rx * vy - ry * vx;
        float wi = 1.f / fmaxf(sqrtf(wx * wx + wy * wy + wz * wz), 1e-12f);
        wx *= wi; wy *= wi; wz *= wi;
        float t1 = nax * nmx + nay * nmy + naz * nmz;
        float t3 = rx * nax + ry * nay + rz * naz;
        float t4 = lx * nmx + ly * nmy + lz * nmz;
        float t6 = nax * vx + nay * vy + naz * vz;
        float t7 = nax * wx + nay * wy + naz * wz;
        float cx = nay * nmz - naz * nmy;
        float cy = naz * nmx - nax * nmz;
        float cz = nax * nmy - nay * nmx;
        float t8 = lx * cx + ly * cy + lz * cz;
        float s1 = lx * (a1.z * lx + a1.w * ly + a2.x * lz)
                 + ly * (a2.y * lx + a2.z * ly + a2.w * lz)
                 + lz * (a3.x * lx + a3.y * ly + a3.z * lz);
        float s2 = lx * (b1.z * lx + b1.w * ly + b2.x * lz)
                 + ly * (b2.y * lx + b2.z * ly + b2.w * lz)
                 + lz * (b3.x * lx + b3.y * ly + b3.z * lz);
        float win[14] = {lx, ly, lz, t1, dot, t3, t4, t3, t6, t7, t8, rn, s1, s2};
        float ya[8];
        #pragma unroll
        for (int o = 0; o < 8; o++) {
            float y = bsm[o];
            #pragma unroll
            for (int c = 0; c < 14; c++) y += wsm[o * 14 + c] * win[c];
            ya[o] = y;
            ls[o] += y; lss[o] += y * y;
        }
        float4* dst = (float4*)&g_y1w[i * 8];
        dst[0] = make_float4(ya[0], ya[1], ya[2], ya[3]);
        dst[1] = make_float4(ya[4], ya[5], ya[6], ya[7]);
    }
    stats_reduce<8>(ls, lss, W1_OFF);
}

// ---------------- w-path layer 2: fp32 in, half out ----------------
__global__ __launch_bounds__(256) void k_w2(const float* __restrict__ ww2,
                                            const float* __restrict__ wb2,
                                            const float* __restrict__ wg1,
                                            const float* __restrict__ wbe1) {
    __shared__ float wsm[64], bsm[8], ssc[8], ssh[8];
    int t = threadIdx.x;
    if (t < 64) wsm[t] = ww2[t];
    if (t < 8)  bsm[t] = wb2[t];
    bn_fin(W1_OFF, 8, INV_NK, wg1, wbe1, ssc, ssh, t);
    __syncthreads();
    float ls[8], lss[8];
    #pragma unroll
    for (int o = 0; o < 8; o++) { ls[o] = 0.f; lss[o] = 0.f; }
    for (int i = blockIdx.x * 256 + t; i < NK; i += gridDim.x * 256) {
        float a[8];
        float4 a0 = *(const float4*)&g_y1w[i * 8];
        float4 a1 = *(const float4*)&g_y1w[i * 8 + 4];
        a[0] = a0.x; a[1] = a0.y; a[2] = a0.z; a[3] = a0.w;
        a[4] = a1.x; a[5] = a1.y; a[6] = a1.z; a[7] = a1.w;
        #pragma unroll
        for (int c = 0; c < 8; c++) a[c] = fmaxf(ssc[c] * a[c] + ssh[c], 0.f);
        float ya[8];
        #pragma unroll
        for (int o = 0; o < 8; o++) {
            float y = bsm[o];
            #pragma unroll
            for (int c = 0; c < 8; c++) y += wsm[o * 8 + c] * a[c];
            ya[o] = y;
            ls[o] += y; lss[o] += y * y;
        }
        uint4 pv;
        pv.x = packh2(ya[0], ya[1]);
        pv.y = packh2(ya[2], ya[3]);
        pv.z = packh2(ya[4], ya[5]);
        pv.w = packh2(ya[6], ya[7]);
        *(uint4*)&g_y2h[i * 4] = pv;
    }
    stats_reduce<8>(ls, lss, W2_OFF);
}

// ---------------- w-path layer 3: stats only ----------------
__global__ __launch_bounds__(256) void k_w3s(const float* __restrict__ ww3,
                                             const float* __restrict__ wb3,
                                             const float* __restrict__ wg2,
                                             const float* __restrict__ wbe2) {
    __shared__ float wsm[128], bsm[16], ssc[8], ssh[8];
    int t = threadIdx.x;
    if (t < 128) wsm[t] = ww3[t];
    if (t < 16)  bsm[t] = wb3[t];
    bn_fin(W2_OFF, 8, INV_NK, wg2, wbe2, ssc, ssh, t);
    __syncthreads();
    float ls[16], lss[16];
    #pragma unroll
    for (int o = 0; o < 16; o++) { ls[o] = 0.f; lss[o] = 0.f; }
    for (int i = blockIdx.x * 256 + t; i < NK; i += gridDim.x * 256) {
        float a[8];
        unpack_y2(i, a);
        #pragma unroll
        for (int c = 0; c < 8; c++) a[c] = fmaxf(ssc[c] * a[c] + ssh[c], 0.f);
        #pragma unroll
        for (int o = 0; o < 16; o++) {
            float y = bsm[o];
            #pragma unroll
            for (int c = 0; c < 8; c++) y += wsm[o * 8 + c] * a[c];
            ls[o] += y; lss[o] += y * y;
        }
    }
    stats_reduce<16>(ls, lss, W3_OFF);
}

// ---------------- fpost (float4-granular) ----------------
__global__ void k_post(const float* __restrict__ fg2, const float* __restrict__ fbe2) {
    __shared__ float ssc[64], ssh[64];
    int t = threadIdx.x;
    bn_fin(F2_OFF, 64, INV_NK, fg2, fbe2, ssc, ssh, t);
    __syncthreads();
    int i = blockIdx.x * 256 + t;
    if (i < NP * 16) {
        int c = (i * 4) & 63;
        float4 v = *(const float4*)&g_g2[i * 4];
        v.x = fmaxf(ssc[c + 0] * v.x + ssh[c + 0], 0.f);
        v.y = fmaxf(ssc[c + 1] * v.y + ssh[c + 1], 0.f);
        v.z = fmaxf(ssc[c + 2] * v.z + ssh[c + 2], 0.f);
        v.w = fmaxf(ssc[c + 3] * v.w + ssh[c + 3], 0.f);
        uint2 pv;
        pv.x = packh2(v.x, v.y);
        pv.y = packh2(v.z, v.w);
        *(uint2*)&g_fph[i * 4] = pv;
    }
}

// ---------------- new = f @ w^T per point, tensor cores (segmented) ----------------
__global__ __launch_bounds__(256) void k_newmma(int nbase,
                                                const int* __restrict__ knn,
                                                const float* __restrict__ ww3,
                                                const float* __restrict__ wb3,
                                                const float* __restrict__ wg2,
                                                const float* __restrict__ wbe2,
                                                const float* __restrict__ wg3,
                                                const float* __restrict__ wbe3) {
    __shared__ __align__(16) __half st[8][16 * 72];
    __shared__ __align__(16) __half ws[8][16 * 24];
    __shared__ float sww3[128], swb3[16], sc3[16], sh3[16], sc2[8], sh2[8];
    int t = threadIdx.x, w = t >> 5, l = t & 31;
    if (t < 128) sww3[t] = ww3[t];
    if (t < 16)  swb3[t] = wb3[t];
    bn_fin(W3_OFF, 16, INV_NK, wg3, wbe3, sc3, sh3, t);
    if (t >= 32 && t < 40) {
        int c = t - 32;
        float m = g_stats[W2_OFF + c] * INV_NK;
        float v = g_stats[W2_OFF + 8 + c] * INV_NK - m * m;
        float s = wg2[c] / sqrtf(v + EPS_BN);
        sc2[c] = s;
        sh2[c] = wbe2[c] - m * s;
    }
    __syncthreads();

    int n = nbase + blockIdx.x * 8 + w;
    int sjv = knn[n * 16 + (l & 15)];
    int jj = __shfl_sync(0xffffffffu, sjv, l >> 1);

    {
        const uint4* src = (const uint4*)(g_fph + (size_t)jj * 64 + (l & 1) * 32);
        uint4* dst = (uint4*)&st[w][(l >> 1) * 72 + (l & 1) * 32];
        dst[0] = src[0]; dst[1] = src[1]; dst[2] = src[2]; dst[3] = src[3];
    }

    if (l < 16) {
        float a[8];
        unpack_y2(n * 16 + l, a);
        #pragma unroll
        for (int c = 0; c < 8; c++) a[c] = fmaxf(sc2[c] * a[c] + sh2[c], 0.f);
        #pragma unroll
        for (int m = 0; m < 16; m++) {
            float y = swb3[m];
            #pragma unroll
            for (int c = 0; c < 8; c++) y += sww3[m * 8 + c] * a[c];
            ws[w][m * 24 + l] = __float2half(fmaxf(sc3[m] * y + sh3[m], 0.f));
        }
    }
    __syncwarp();

    unsigned bf[2][2];
    #pragma unroll
    for (int mg = 0; mg < 2; mg++) {
        int q = l & 15;
        unsigned addr = smem_u32x(&ws[w][(mg * 8 + (q & 7)) * 24 + (q >> 3) * 8]);
        ldsm_x2(bf[mg][0], bf[mg][1], addr);
    }

    float d[4][2][4] = {};
    int matid = l >> 3;
    int krow = (l & 7) + ((matid >> 1) << 3);
    int coff = (matid & 1) * 8;

    #pragma unroll
    for (int hg = 0; hg < 4; hg++) {
        unsigned a0, a1, a2, a3;
        unsigned addr = smem_u32x(&st[w][krow * 72 + hg * 16 + coff]);
        ldsm_x4_trans(a0, a1, a2, a3, addr);
        #pragma unroll
        for (int mg = 0; mg < 2; mg++)
            mma_f16(d[hg][mg], a0, a1, a2, a3, bf[mg][0], bf[mg][1]);
    }

    int g = l >> 2, tt = l & 3;
    unsigned* row = g_newh + (size_t)n * 512;
    #pragma unroll
    for (int hg = 0; hg < 4; hg++) {
        int h = hg * 16 + g;
        #pragma unroll
        for (int mg = 0; mg < 2; mg++) {
            int pos = wperm(mg * 4 + tt);
            row[h * 8 + pos]       = packh2(d[hg][mg][0], d[hg][mg][1]);
            row[(h + 8) * 8 + pos] = packh2(d[hg][mg][2], d[hg][mg][3]);
        }
    }
}

// ---------------- GEMM (segmented) ----------------
#define GP 36
#define GA (128*GP)
#define GB (64*GP)
#define SMEM_G ((2*GA + 2*GB)*4)

__global__ __launch_bounds__(256, 3) void k_gemm(int nbase, const float* __restrict__ lb) {
    extern __shared__ unsigned sm[];
    unsigned* As[2] = { sm, sm + GA };
    unsigned* Bs[2] = { sm + 2 * GA, sm + 2 * GA + GB };
    __shared__ float sred[128];
    int t = threadIdx.x;
    int rbase = nbase + blockIdx.x * 128;
    int lane = t & 31, grp = lane >> 2, qid = lane & 3;
    int m0 = (t >> 5) * 16;

    if (rbase + 128 > NP) {
        for (int i = t; i < 2 * GA; i += 256) sm[i] = 0u;
        __syncthreads();
    }
    if (t < 128) sred[t] = 0.f;

    float cf[8][4];
    #pragma unroll
    for (int nt = 0; nt < 8; nt++)
        #pragma unroll
        for (int j = 0; j < 4; j++) cf[nt][j] = 0.f;

    auto load = [&](int buf, int s) {
        int kc = s * 32;
        #pragma unroll
        for (int r4 = 0; r4 < 4; r4++) {
            int seg = t + r4 * 256;
            int row = seg >> 3, w16 = seg & 7;
            if (rbase + row < NP)
                cp16(As[buf] + row * GP + w16 * 4,
                     g_newh + (size_t)(rbase + row) * 512 + kc + w16 * 4);
        }
        #pragma unroll
        for (int r2 = 0; r2 < 2; r2++) {
            int seg = t + r2 * 256;
            int row = seg >> 3, w16 = seg & 7;
            cp16(Bs[buf] + row * GP + w16 * 4,
                 g_lwth + row * 512 + kc + w16 * 4);
        }
        asm volatile("cp.async.commit_group;");
    };

    load(0, 0);
    int cur = 0;
    for (int s = 0; s < 16; s++) {
        if (s < 15) {
            load(cur ^ 1, s + 1);
            asm volatile("cp.async.wait_group 1;");
        } else {
            asm volatile("cp.async.wait_group 0;");
        }
        __syncthreads();
        unsigned* A = As[cur];
        unsigned* B = Bs[cur];
        #pragma unroll
        for (int ks = 0; ks < 4; ks++) {
            uint2 aLo = *(uint2*)&A[(m0 + grp) * GP + ks * 8 + qid * 2];
            uint2 aHi = *(uint2*)&A[(m0 + grp + 8) * GP + ks * 8 + qid * 2];
            #pragma unroll
            for (int nt = 0; nt < 8; nt++) {
                uint2 b = *(uint2*)&B[(nt * 8 + grp) * GP + ks * 8 + qid * 2];
                mma_f16(cf[nt], aLo.x, aHi.x, aLo.y, aHi.y, b.x, b.y);
            }
        }
        __syncthreads();
        cur ^= 1;
    }

    int r0 = rbase + m0 + grp, r1 = r0 + 8;
    bool v0 = r0 < NP, v1 = r1 < NP;
    #pragma unroll
    for (int nt = 0; nt < 8; nt++) {
        int c0 = nt * 8 + 2 * qid;
        float b0v = __ldg(&lb[c0]), b1v = __ldg(&lb[c0 + 1]);
        float z0 = cf[nt][0] + b0v, z1 = cf[nt][1] + b1v;
        float z2 = cf[nt][2] + b0v, z3 = cf[nt][3] + b1v;
        float s0 = 0.f, s1 = 0.f, q0 = 0.f, q1 = 0.f;
        if (v0) {
            *(float2*)&g_z[r0 * 64 + c0] = make_float2(z0, z1);
            s0 += z0; s1 += z1; q0 += z0 * z0; q1 += z1 * z1;
        }
        if (v1) {
            *(float2*)&g_z[r1 * 64 + c0] = make_float2(z2, z3);
            s0 += z2; s1 += z3; q0 += z2 * z2; q1 += z3 * z3;
        }
        qred4(s0, s1, q0, q1);
        if (lane < 4) {
            atomicAdd(&sred[c0], s0);
            atomicAdd(&sred[c0 + 1], s1);
            atomicAdd(&sred[64 + c0], q0);
            atomicAdd(&sred[64 + c0 + 1], q1);
        }
    }
    __syncthreads();
    if (t < 128) atomicAdd(&g_stats[Z_OFF + t], sred[t]);
}

// ---------------- final BN + relu -> output (float4) ----------------
__global__ void k_out(float* __restrict__ out,
                      const float* __restrict__ bng, const float* __restrict__ bnb) {
    __shared__ float ssc[64], ssh[64];
    int t = threadIdx.x;
    bn_fin(Z_OFF, 64, INV_N, bng, bnb, ssc, ssh, t);
    __syncthreads();
    int i = blockIdx.x * 256 + t;
    if (i < NP * 16) {
        int c = (i * 4) & 63;
        float4 v = *(const float4*)&g_z[i * 4];
        v.x = fmaxf(ssc[c + 0] * v.x + ssh[c + 0], 0.f);
        v.y = fmaxf(ssc[c + 1] * v.y + ssh[c + 1], 0.f);
        v.z = fmaxf(ssc[c + 2] * v.z + ssh[c + 2], 0.f);
        v.w = fmaxf(ssc[c + 3] * v.w + ssh[c + 3], 0.f);
        *(float4*)&out[i * 4] = v;
    }
}

// ---------------- stream/event infra ----------------
static cudaStream_t g_sF = nullptr;
static cudaEvent_t  g_eFork = nullptr, g_eJoin = nullptr;
static cudaEvent_t  g_eN0 = nullptr, g_eN1 = nullptr, g_eG = nullptr;
static int g_stream_init = ([]() {
    cudaStreamCreateWithFlags(&g_sF, cudaStreamNonBlocking);
    cudaEventCreateWithFlags(&g_eFork, cudaEventDisableTiming);
    cudaEventCreateWithFlags(&g_eJoin, cudaEventDisableTiming);
    cudaEventCreateWithFlags(&g_eN0, cudaEventDisableTiming);
    cudaEventCreateWithFlags(&g_eN1, cudaEventDisableTiming);
    cudaEventCreateWithFlags(&g_eG, cudaEventDisableTiming);
    return 0;
})();

// ---------------- launch ----------------
extern "C" void kernel_launch(void* const* d_in, const int* in_sizes, int n_in,
                              void* d_out, int out_size) {
    const float* xyz   = (const float*)d_in[0];
    const float* cov   = (const float*)d_in[1];
    const float* feats = (const float*)d_in[2];
    const int*   knn   = (const int*)  d_in[3];
    const float* fw1 = (const float*)d_in[4];
    const float* fb1 = (const float*)d_in[5];
    const float* fg1 = (const float*)d_in[6];
    const float* fbe1 = (const float*)d_in[7];
    const float* fw2 = (const float*)d_in[8];
    const float* fb2 = (const float*)d_in[9];
    const float* fg2 = (const float*)d_in[10];
    const float* fbe2 = (const float*)d_in[11];
    const float* ww1 = (const float*)d_in[12];
    const float* wb1 = (const float*)d_in[13];
    const float* wg1 = (const float*)d_in[14];
    const float* wbe1 = (const float*)d_in[15];
    const float* ww2 = (const float*)d_in[16];
    const float* wb2 = (const float*)d_in[17];
    const float* wg2 = (const float*)d_in[18];
    const float* wbe2 = (const float*)d_in[19];
    const float* ww3 = (const float*)d_in[20];
    const float* wb3 = (const float*)d_in[21];
    const float* wg3 = (const float*)d_in[22];
    const float* wbe3 = (const float*)d_in[23];
    const float* lin_w = (const float*)d_in[24];
    const float* lin_b = (const float*)d_in[25];
    const float* bng = (const float*)d_in[26];
    const float* bnb = (const float*)d_in[27];
    float* out = (float*)d_out;

    float* d_g1; cudaGetSymbolAddress((void**)&d_g1, g_g1);
    float* d_g2; cudaGetSymbolAddress((void**)&d_g2, g_g2);

    cudaFuncSetAttribute(k_gemm, cudaFuncAttributeMaxDynamicSharedMemorySize, SMEM_G);

    cudaStream_t sF = g_sF;
    const int NBLK = (NP + 127) / 128;
    const int NB0 = SEG0 / 128;
    const int NB1 = NBLK - NB0;
    const int NM0 = SEG0 / 8;
    const int NM1 = (NP - SEG0) / 8;

    // ---- common init on main stream ----
    k_zero<<<(NP + 255) / 256, 256>>>();
    cudaEventRecord(g_eFork, 0);
    cudaStreamWaitEvent(sF, g_eFork, 0);

    // ---- w-path on main stream ----
    k_geo<<<(NP + 255) / 256, 256>>>(xyz, cov, feats);
    k_w1<<<2048, 256>>>(knn, ww1, wb1);
    k_w2<<<2048, 256>>>(ww2, wb2, wg1, wbe1);
    k_w3s<<<2048, 256>>>(ww3, wb3, wg2, wbe2);
    k_preph<<<128, 256>>>(lin_w);

    // ---- fork: counts + f-path on sF (concurrent with w-path) ----
    k_cnt<<<(NK + 255) / 256, 256, 0, sF>>>(knn);
    k_fmma32<0><<<NBLK, 256, 0, sF>>>(feats, fw1, fb1, d_g1, F1_OFF, 0, nullptr, nullptr);
    k_fmma32<1><<<NBLK, 256, 0, sF>>>(d_g1, fw2, fb2, d_g2, F2_OFF, F1_OFF, fg1, fbe1);
    k_post<<<(NP * 16 + 255) / 256, 256, 0, sF>>>(fg2, fbe2);
    cudaEventRecord(g_eJoin, sF);

    // ---- join: main waits for f-chain ----
    cudaStreamWaitEvent(0, g_eJoin, 0);

    // ---- segmented einsum + GEMM with cross-stream overlap ----
    k_newmma<<<NM0, 256>>>(0, knn, ww3, wb3, wg2, wbe2, wg3, wbe3);
    cudaEventRecord(g_eN0, 0);
    k_newmma<<<NM1, 256>>>(SEG0, knn, ww3, wb3, wg2, wbe2, wg3, wbe3);
    cudaEventRecord(g_eN1, 0);

    cudaStreamWaitEvent(sF, g_eN0, 0);
    k_gemm<<<NB0, 256, SMEM_G, sF>>>(0, lin_b);
    cudaStreamWaitEvent(sF, g_eN1, 0);
    k_gemm<<<NB1, 256, SMEM_G, sF>>>(SEG0, lin_b);
    cudaEventRecord(g_eG, sF);

    cudaStreamWaitEvent(0, g_eG, 0);
    k_out<<<(NP * 16 + 255) / 256, 256>>>(out, bng, bnb);
}